// round 12
// baseline (speedup 1.0000x reference)
#include <cuda_runtime.h>
#include <cuda_fp16.h>

#define NMAX   100000
#define EMAX   1600000
#define HDIM   32
#define STRIDE 64                              // padded-CSR slots per node

// Scratch (allocation-free rule: __device__ globals).
// Invariant: g_deg and g_ovfn are zero at every kernel_launch entry
// (module-load zero-init; node_prep restores after consuming them).
__device__ int    g_deg[NMAX];                 // in-degree (excl. self-loop)
__device__ int    g_degc[NMAX];                // degree copy for agg
__device__ float  g_dis[NMAX];                 // rsqrt(deg+1)
__device__ int    g_csrp[(size_t)NMAX * STRIDE]; // padded CSR: src indices
__device__ int    g_ovfn;                      // overflow count (build)
__device__ int    g_ovfc;                      // overflow count (stable copy)
__device__ int2   g_ovf[EMAX];                 // overflow (dst, src)
__device__ __half g_tmp[(size_t)NMAX * HDIM];  // dis[i] * (f(in_i) @ W), fp16
__device__ __half g_acc16[(size_t)NMAX * HDIM];// layer-1 output, fp16

// int64 read of an int32 buffer fuses two indices -> out of [0,n) w.h.p.
__device__ __forceinline__ int detect_is32(const void* ei, int n, int* s_is32) {
    if (threadIdx.x < 32) {
        long long v = ((const long long*)ei)[threadIdx.x];
        unsigned m = __ballot_sync(0xffffffffu, v < 0 || v >= (long long)n);
        if (threadIdx.x == 0) *s_is32 = m ? 1 : 0;
    }
    __syncthreads();
    return *s_is32;
}

// ---------------- build: degree histogram + padded-CSR fill in ONE pass ----------------

__global__ void build_kernel(const void* __restrict__ ei, int e, int n) {
    __shared__ int s_is32;
    int is32 = detect_is32(ei, n, &s_is32);
    int i = blockIdx.x * blockDim.x + threadIdx.x;
    if (i >= e) return;
    int s, d;
    if (is32) {
        const int* p = (const int*)ei;
        s = p[i]; d = p[e + i];
    } else {
        const long long* p = (const long long*)ei;
        s = (int)p[i]; d = (int)p[e + i];
    }
    int pos = atomicAdd(&g_deg[d], 1);         // rank = slot (any perm ok)
    if (pos < STRIDE) {
        g_csrp[(size_t)d * STRIDE + pos] = s;
    } else {                                   // ~never on this dataset
        int k = atomicAdd(&g_ovfn, 1);
        g_ovf[k] = make_int2(d, s);
    }
}

// ---------------- node prep: dis, degree copy, invariant restore ----------------

__global__ void node_prep_kernel(int n) {
    int i = blockIdx.x * blockDim.x + threadIdx.x;
    if (i == 0) { g_ovfc = g_ovfn; g_ovfn = 0; }
    if (i >= n) return;
    int v = g_deg[i];
    g_dis[i]  = rsqrtf((float)(v + 1));        // +1: self-loop
    g_degc[i] = v;
    g_deg[i]  = 0;                             // restore invariant for next call
}

// ---------------- fused GEMM: tmp[node] = dis[node] * (f(rowin) @ W), fp16 ----------------
// 2 threads per node (j-halves of 16). IN16: fp16 input rows; RELU_BIAS on load.

template <bool IN16, bool RELU_BIAS>
__global__ void __launch_bounds__(256)
mm_kernel(const void* __restrict__ in, const float* __restrict__ W,
          const float* __restrict__ b, const float* __restrict__ dis,
          __half* __restrict__ tmp, int n)
{
    __shared__ float Ws[32][32];
    __shared__ float bs[32];
    int t = threadIdx.x;
    for (int i = t; i < 1024; i += 256) Ws[i >> 5][i & 31] = W[i];
    if (RELU_BIAS && t < 32) bs[t] = b[t];
    __syncthreads();

    int node = blockIdx.x * 128 + (t >> 1);
    int half = t & 1;                      // output j-range: half*16 .. half*16+15
    if (node >= n) return;

    float xr[32];
    if (IN16) {
        const uint4* xin = reinterpret_cast<const uint4*>((const __half*)in + (size_t)node * HDIM);
#pragma unroll
        for (int q = 0; q < 4; q++) {
            uint4 u = xin[q];
            unsigned w[4] = {u.x, u.y, u.z, u.w};
#pragma unroll
            for (int j = 0; j < 4; j++) {
                float2 f = __half22float2(*reinterpret_cast<__half2*>(&w[j]));
                xr[q * 8 + j * 2 + 0] = f.x;
                xr[q * 8 + j * 2 + 1] = f.y;
            }
        }
    } else {
        const float4* xin = reinterpret_cast<const float4*>((const float*)in + (size_t)node * HDIM);
#pragma unroll
        for (int q = 0; q < 8; q++) {
            float4 v = xin[q];
            xr[4 * q + 0] = v.x; xr[4 * q + 1] = v.y;
            xr[4 * q + 2] = v.z; xr[4 * q + 3] = v.w;
        }
    }
    if (RELU_BIAS) {
#pragma unroll
        for (int j = 0; j < 32; j++) xr[j] = fmaxf(xr[j] + bs[j], 0.0f);
    }

    int jb = half * 16;
    float o[16];
#pragma unroll
    for (int j = 0; j < 16; j++) o[j] = 0.0f;
#pragma unroll
    for (int k = 0; k < 32; k++) {
        float xv = xr[k];
#pragma unroll
        for (int j = 0; j < 16; j++) o[j] = fmaf(xv, Ws[k][jb + j], o[j]);
    }

    float d = dis[node];
    uint4 u;
    {
        __half2 h0 = __floats2half2_rn(o[0] * d,  o[1] * d);
        __half2 h1 = __floats2half2_rn(o[2] * d,  o[3] * d);
        __half2 h2 = __floats2half2_rn(o[4] * d,  o[5] * d);
        __half2 h3 = __floats2half2_rn(o[6] * d,  o[7] * d);
        u.x = *reinterpret_cast<unsigned*>(&h0);
        u.y = *reinterpret_cast<unsigned*>(&h1);
        u.z = *reinterpret_cast<unsigned*>(&h2);
        u.w = *reinterpret_cast<unsigned*>(&h3);
    }
    uint4 u2;
    {
        __half2 h0 = __floats2half2_rn(o[8] * d,  o[9] * d);
        __half2 h1 = __floats2half2_rn(o[10] * d, o[11] * d);
        __half2 h2 = __floats2half2_rn(o[12] * d, o[13] * d);
        __half2 h3 = __floats2half2_rn(o[14] * d, o[15] * d);
        u2.x = *reinterpret_cast<unsigned*>(&h0);
        u2.y = *reinterpret_cast<unsigned*>(&h1);
        u2.z = *reinterpret_cast<unsigned*>(&h2);
        u2.w = *reinterpret_cast<unsigned*>(&h3);
    }
    uint4* tp = reinterpret_cast<uint4*>(tmp + (size_t)node * HDIM + jb);
    tp[0] = u;
    tp[1] = u2;
}

// ---------------- aggregate (pure gather, padded CSR, fp16 msgs + HADD2) ----------------
// 4 nodes per warp: 8-lane group per node, lane = 4 features (uint2 of half2s).
// Each 8-edge batch accumulates in half2 (2 HADD2/edge) and folds into fp32
// once per batch: ~5.3 warp-inst/edge vs ~10.5 for per-edge conversion.
// OUT16: write fp16 row without bias (layer 1). Else fp32 + bias + relu.

template <bool OUT16>
__global__ void __launch_bounds__(256)
agg_kernel(const uint2* __restrict__ tmp4, void* __restrict__ out,
           const float* __restrict__ b, int n)
{
    int gid  = blockIdx.x * 256 + threadIdx.x;
    int node = gid >> 3;                 // 8 lanes per node
    int li   = threadIdx.x & 7;
    bool valid = node < n;
    if (!valid) node = n - 1;            // keep lanes converged for shfl

    int deg = g_degc[node];
    int end = deg < STRIDE ? deg : STRIDE;
    const int* row = g_csrp + (size_t)node * STRIDE;

    uint2 sv = __ldg(&tmp4[(size_t)node * 8 + li]);        // self-loop term
    float2 a0 = __half22float2(*reinterpret_cast<__half2*>(&sv.x));
    float2 a1 = __half22float2(*reinterpret_cast<__half2*>(&sv.y));

    const __half2 z = __float2half2_rn(0.0f);
    int k = 0;

    // full batches: no bounds checks
    for (; k + 8 <= end; k += 8) {
        int src = row[k + li];
        __half2 p0 = z, p1 = z;
#pragma unroll
        for (int j = 0; j < 8; j++) {
            int ss = __shfl_sync(0xffffffffu, src, j, 8);
            uint2 v = __ldg(&tmp4[(size_t)ss * 8 + li]);
            p0 = __hadd2(p0, *reinterpret_cast<__half2*>(&v.x));
            p1 = __hadd2(p1, *reinterpret_cast<__half2*>(&v.y));
        }
        float2 f0 = __half22float2(p0);
        float2 f1 = __half22float2(p1);
        a0.x += f0.x; a0.y += f0.y;
        a1.x += f1.x; a1.y += f1.y;
    }

    // tail batch (cnt in 1..7)
    if (k < end) {
        int cnt = end - k;
        int idx = k + li;
        int src = row[idx < end ? idx : (end - 1)];
        __half2 p0 = z, p1 = z;
#pragma unroll
        for (int j = 0; j < 7; j++) {
            int ss = __shfl_sync(0xffffffffu, src, j, 8);
            if (j < cnt) {
                uint2 v = __ldg(&tmp4[(size_t)ss * 8 + li]);
                p0 = __hadd2(p0, *reinterpret_cast<__half2*>(&v.x));
                p1 = __hadd2(p1, *reinterpret_cast<__half2*>(&v.y));
            }
        }
        float2 f0 = __half22float2(p0);
        float2 f1 = __half22float2(p1);
        a0.x += f0.x; a0.y += f0.y;
        a1.x += f1.x; a1.y += f1.y;
    }

    if (deg > STRIDE) {                  // overflow path: ~never taken
        int c = g_ovfc;
        for (int i = 0; i < c; i++) {
            int2 o = g_ovf[i];
            if (o.x == node) {
                uint2 v = __ldg(&tmp4[(size_t)o.y * 8 + li]);
                float2 v0 = __half22float2(*reinterpret_cast<__half2*>(&v.x));
                float2 v1 = __half22float2(*reinterpret_cast<__half2*>(&v.y));
                a0.x += v0.x; a0.y += v0.y;
                a1.x += v1.x; a1.y += v1.y;
            }
        }
    }

    float dn = g_dis[node];
    if (!valid) return;
    if (OUT16) {
        __half2 h0 = __floats2half2_rn(a0.x * dn, a0.y * dn);
        __half2 h1 = __floats2half2_rn(a1.x * dn, a1.y * dn);
        uint2 u;
        u.x = *reinterpret_cast<unsigned*>(&h0);
        u.y = *reinterpret_cast<unsigned*>(&h1);
        reinterpret_cast<uint2*>(out)[(size_t)node * 8 + li] = u;
    } else {
        float4 bb = reinterpret_cast<const float4*>(b)[li];
        float4 r = make_float4(fmaxf(a0.x * dn + bb.x, 0.0f),
                               fmaxf(a0.y * dn + bb.y, 0.0f),
                               fmaxf(a1.x * dn + bb.z, 0.0f),
                               fmaxf(a1.y * dn + bb.w, 0.0f));
        reinterpret_cast<float4*>(out)[(size_t)node * 8 + li] = r;
    }
}

// ---------------- launch ----------------

extern "C" void kernel_launch(void* const* d_in, const int* in_sizes, int n_in,
                              void* d_out, int out_size)
{
    const float* x   = (const float*)d_in[0];
    const void*  ei  = d_in[1];
    const float* W1  = (const float*)d_in[2];
    const float* b1  = (const float*)d_in[3];
    const float* W2  = (const float*)d_in[4];
    const float* b2  = (const float*)d_in[5];
    float*       out = (float*)d_out;

    int n = in_sizes[0] / HDIM;       // 100000
    int e = in_sizes[1] / 2;          // 1600000

    void *p_tmp, *p_acc, *p_dis;
    cudaGetSymbolAddress(&p_tmp, g_tmp);
    cudaGetSymbolAddress(&p_acc, g_acc16);
    cudaGetSymbolAddress(&p_dis, g_dis);
    uint2*  tmp4  = (uint2*)p_tmp;
    __half* tmp   = (__half*)p_tmp;
    __half* acc16 = (__half*)p_acc;
    float*  dis   = (float*)p_dis;

    int nb_n = (n + 255) / 256;
    int nb_e = (e + 255) / 256;
    int nb_m = (n + 127) / 128;               // 2 threads per node
    int nb_g = (n * 8 + 255) / 256;           // 8 lanes per node

    // padded-CSR build + normalization (amortized over both layers)
    build_kernel    <<<nb_e, 256>>>(ei, e, n);
    node_prep_kernel<<<nb_n, 256>>>(n);

    // layer 1
    mm_kernel<false, false><<<nb_m, 256>>>(x, W1, nullptr, dis, tmp, n);
    agg_kernel<true>       <<<nb_g, 256>>>(tmp4, acc16, nullptr, n);

    // layer 2 (b1+ReLU fused into GEMM load; b2+ReLU fused into agg epilogue)
    mm_kernel<true, true>  <<<nb_m, 256>>>(acc16, W2, b1, dis, tmp, n);
    agg_kernel<false>      <<<nb_g, 256>>>(tmp4, out, b2, n);
}

// round 13
// speedup vs baseline: 1.2671x; 1.2671x over previous
#include <cuda_runtime.h>
#include <cuda_fp16.h>

#define NMAX   100000
#define EMAX   1600000
#define HDIM   32
#define STRIDE 64                              // padded-CSR slots per node

// Scratch (allocation-free rule: __device__ globals).
// Invariant: g_deg and g_ovfn are zero at every kernel_launch entry
// (module-load zero-init; node_prep restores after consuming them).
__device__ int    g_deg[NMAX];                 // in-degree (excl. self-loop)
__device__ int    g_degc[NMAX];                // degree copy for agg
__device__ float  g_dis[NMAX];                 // rsqrt(deg+1)
__device__ int    g_csrp[(size_t)NMAX * STRIDE]; // padded CSR: src indices
__device__ int    g_ovfn;                      // overflow count (build)
__device__ int    g_ovfc;                      // overflow count (stable copy)
__device__ int2   g_ovf[EMAX];                 // overflow (dst, src)
__device__ __half g_tmp[(size_t)NMAX * HDIM];  // dis[i] * (f(in_i) @ W), fp16
__device__ __half g_acc16[(size_t)NMAX * HDIM];// layer-1 output, fp16

// int64 read of an int32 buffer fuses two indices -> out of [0,n) w.h.p.
__device__ __forceinline__ int detect_is32(const void* ei, int n, int* s_is32) {
    if (threadIdx.x < 32) {
        long long v = ((const long long*)ei)[threadIdx.x];
        unsigned m = __ballot_sync(0xffffffffu, v < 0 || v >= (long long)n);
        if (threadIdx.x == 0) *s_is32 = m ? 1 : 0;
    }
    __syncthreads();
    return *s_is32;
}

// ---------------- build: degree histogram + padded-CSR fill in ONE pass ----------------

__global__ void build_kernel(const void* __restrict__ ei, int e, int n) {
    __shared__ int s_is32;
    int is32 = detect_is32(ei, n, &s_is32);
    int i = blockIdx.x * blockDim.x + threadIdx.x;
    if (i >= e) return;
    int s, d;
    if (is32) {
        const int* p = (const int*)ei;
        s = p[i]; d = p[e + i];
    } else {
        const long long* p = (const long long*)ei;
        s = (int)p[i]; d = (int)p[e + i];
    }
    int pos = atomicAdd(&g_deg[d], 1);         // rank = slot (any perm ok)
    if (pos < STRIDE) {
        g_csrp[(size_t)d * STRIDE + pos] = s;
    } else {                                   // ~never on this dataset
        int k = atomicAdd(&g_ovfn, 1);
        g_ovf[k] = make_int2(d, s);
    }
}

// ---------------- node prep: dis, degree copy, invariant restore ----------------

__global__ void node_prep_kernel(int n) {
    int i = blockIdx.x * blockDim.x + threadIdx.x;
    if (i == 0) { g_ovfc = g_ovfn; g_ovfn = 0; }
    if (i >= n) return;
    int v = g_deg[i];
    g_dis[i]  = rsqrtf((float)(v + 1));        // +1: self-loop
    g_degc[i] = v;
    g_deg[i]  = 0;                             // restore invariant for next call
}

// ---------------- fused GEMM: tmp[node] = dis[node] * (f(rowin) @ W), fp16 ----------------
// 2 threads per node (j-halves of 16). IN16: fp16 input rows; RELU_BIAS on load.

template <bool IN16, bool RELU_BIAS>
__global__ void __launch_bounds__(256)
mm_kernel(const void* __restrict__ in, const float* __restrict__ W,
          const float* __restrict__ b, const float* __restrict__ dis,
          __half* __restrict__ tmp, int n)
{
    __shared__ float Ws[32][32];
    __shared__ float bs[32];
    int t = threadIdx.x;
    for (int i = t; i < 1024; i += 256) Ws[i >> 5][i & 31] = W[i];
    if (RELU_BIAS && t < 32) bs[t] = b[t];
    __syncthreads();

    int node = blockIdx.x * 128 + (t >> 1);
    int half = t & 1;                      // output j-range: half*16 .. half*16+15
    if (node >= n) return;

    float xr[32];
    if (IN16) {
        const uint4* xin = reinterpret_cast<const uint4*>((const __half*)in + (size_t)node * HDIM);
#pragma unroll
        for (int q = 0; q < 4; q++) {
            uint4 u = xin[q];
            unsigned w[4] = {u.x, u.y, u.z, u.w};
#pragma unroll
            for (int j = 0; j < 4; j++) {
                float2 f = __half22float2(*reinterpret_cast<__half2*>(&w[j]));
                xr[q * 8 + j * 2 + 0] = f.x;
                xr[q * 8 + j * 2 + 1] = f.y;
            }
        }
    } else {
        const float4* xin = reinterpret_cast<const float4*>((const float*)in + (size_t)node * HDIM);
#pragma unroll
        for (int q = 0; q < 8; q++) {
            float4 v = xin[q];
            xr[4 * q + 0] = v.x; xr[4 * q + 1] = v.y;
            xr[4 * q + 2] = v.z; xr[4 * q + 3] = v.w;
        }
    }
    if (RELU_BIAS) {
#pragma unroll
        for (int j = 0; j < 32; j++) xr[j] = fmaxf(xr[j] + bs[j], 0.0f);
    }

    int jb = half * 16;
    float o[16];
#pragma unroll
    for (int j = 0; j < 16; j++) o[j] = 0.0f;
#pragma unroll
    for (int k = 0; k < 32; k++) {
        float xv = xr[k];
#pragma unroll
        for (int j = 0; j < 16; j++) o[j] = fmaf(xv, Ws[k][jb + j], o[j]);
    }

    float d = dis[node];
    uint4 u;
    {
        __half2 h0 = __floats2half2_rn(o[0] * d,  o[1] * d);
        __half2 h1 = __floats2half2_rn(o[2] * d,  o[3] * d);
        __half2 h2 = __floats2half2_rn(o[4] * d,  o[5] * d);
        __half2 h3 = __floats2half2_rn(o[6] * d,  o[7] * d);
        u.x = *reinterpret_cast<unsigned*>(&h0);
        u.y = *reinterpret_cast<unsigned*>(&h1);
        u.z = *reinterpret_cast<unsigned*>(&h2);
        u.w = *reinterpret_cast<unsigned*>(&h3);
    }
    uint4 u2;
    {
        __half2 h0 = __floats2half2_rn(o[8] * d,  o[9] * d);
        __half2 h1 = __floats2half2_rn(o[10] * d, o[11] * d);
        __half2 h2 = __floats2half2_rn(o[12] * d, o[13] * d);
        __half2 h3 = __floats2half2_rn(o[14] * d, o[15] * d);
        u2.x = *reinterpret_cast<unsigned*>(&h0);
        u2.y = *reinterpret_cast<unsigned*>(&h1);
        u2.z = *reinterpret_cast<unsigned*>(&h2);
        u2.w = *reinterpret_cast<unsigned*>(&h3);
    }
    uint4* tp = reinterpret_cast<uint4*>(tmp + (size_t)node * HDIM + jb);
    tp[0] = u;
    tp[1] = u2;
}

// ---------------- aggregate (pure gather, padded CSR, fp16 msgs) ----------------
// 4 nodes per warp: 8-lane group per node, lane = 4 features (uint2 of half2s).
// No shfl: indices are read group-uniformly (same L1 line). Full batches
// front-load 8 indices then 8 gathers (explicit MLP=8), then 4 independent
// fp32 accumulation chains (the ILP structure that measured fastest).
// OUT16: write fp16 row without bias (layer 1). Else fp32 + bias + relu.

template <bool OUT16>
__global__ void __launch_bounds__(256)
agg_kernel(const uint2* __restrict__ tmp4, void* __restrict__ out,
           const float* __restrict__ b, int n)
{
    int gid  = blockIdx.x * 256 + threadIdx.x;
    int node = gid >> 3;                 // 8 lanes per node
    int li   = threadIdx.x & 7;
    if (node >= n) return;               // no shfl -> free exit

    int deg = g_degc[node];
    int end = deg < STRIDE ? deg : STRIDE;
    const int* row = g_csrp + (size_t)node * STRIDE;

    uint2 sv = __ldg(&tmp4[(size_t)node * 8 + li]);        // self-loop term
    float2 a0 = __half22float2(*reinterpret_cast<__half2*>(&sv.x));
    float2 a1 = __half22float2(*reinterpret_cast<__half2*>(&sv.y));

    int k = 0;
    // full batches: no predication, explicit load front-batching
    for (; k + 8 <= end; k += 8) {
        int ss[8];
#pragma unroll
        for (int j = 0; j < 8; j++) ss[j] = __ldg(&row[k + j]);
        uint2 v[8];
#pragma unroll
        for (int j = 0; j < 8; j++) v[j] = __ldg(&tmp4[(size_t)ss[j] * 8 + li]);
#pragma unroll
        for (int j = 0; j < 8; j++) {
            float2 v0 = __half22float2(*reinterpret_cast<__half2*>(&v[j].x));
            float2 v1 = __half22float2(*reinterpret_cast<__half2*>(&v[j].y));
            a0.x += v0.x; a0.y += v0.y;
            a1.x += v1.x; a1.y += v1.y;
        }
    }
    // tail (0..7 edges), iterations independent
    for (; k < end; k++) {
        int ss = __ldg(&row[k]);
        uint2 v = __ldg(&tmp4[(size_t)ss * 8 + li]);
        float2 v0 = __half22float2(*reinterpret_cast<__half2*>(&v.x));
        float2 v1 = __half22float2(*reinterpret_cast<__half2*>(&v.y));
        a0.x += v0.x; a0.y += v0.y;
        a1.x += v1.x; a1.y += v1.y;
    }

    if (deg > STRIDE) {                  // overflow path: ~never taken
        int c = g_ovfc;
        for (int i = 0; i < c; i++) {
            int2 o = g_ovf[i];
            if (o.x == node) {
                uint2 v = __ldg(&tmp4[(size_t)o.y * 8 + li]);
                float2 v0 = __half22float2(*reinterpret_cast<__half2*>(&v.x));
                float2 v1 = __half22float2(*reinterpret_cast<__half2*>(&v.y));
                a0.x += v0.x; a0.y += v0.y;
                a1.x += v1.x; a1.y += v1.y;
            }
        }
    }

    float dn = g_dis[node];
    if (OUT16) {
        __half2 h0 = __floats2half2_rn(a0.x * dn, a0.y * dn);
        __half2 h1 = __floats2half2_rn(a1.x * dn, a1.y * dn);
        uint2 u;
        u.x = *reinterpret_cast<unsigned*>(&h0);
        u.y = *reinterpret_cast<unsigned*>(&h1);
        reinterpret_cast<uint2*>(out)[(size_t)node * 8 + li] = u;
    } else {
        float4 bb = reinterpret_cast<const float4*>(b)[li];
        float4 r = make_float4(fmaxf(a0.x * dn + bb.x, 0.0f),
                               fmaxf(a0.y * dn + bb.y, 0.0f),
                               fmaxf(a1.x * dn + bb.z, 0.0f),
                               fmaxf(a1.y * dn + bb.w, 0.0f));
        reinterpret_cast<float4*>(out)[(size_t)node * 8 + li] = r;
    }
}

// ---------------- launch ----------------

extern "C" void kernel_launch(void* const* d_in, const int* in_sizes, int n_in,
                              void* d_out, int out_size)
{
    const float* x   = (const float*)d_in[0];
    const void*  ei  = d_in[1];
    const float* W1  = (const float*)d_in[2];
    const float* b1  = (const float*)d_in[3];
    const float* W2  = (const float*)d_in[4];
    const float* b2  = (const float*)d_in[5];
    float*       out = (float*)d_out;

    int n = in_sizes[0] / HDIM;       // 100000
    int e = in_sizes[1] / 2;          // 1600000

    void *p_tmp, *p_acc, *p_dis;
    cudaGetSymbolAddress(&p_tmp, g_tmp);
    cudaGetSymbolAddress(&p_acc, g_acc16);
    cudaGetSymbolAddress(&p_dis, g_dis);
    uint2*  tmp4  = (uint2*)p_tmp;
    __half* tmp   = (__half*)p_tmp;
    __half* acc16 = (__half*)p_acc;
    float*  dis   = (float*)p_dis;

    int nb_n = (n + 255) / 256;
    int nb_e = (e + 255) / 256;
    int nb_m = (n + 127) / 128;               // 2 threads per node
    int nb_g = (n * 8 + 255) / 256;           // 8 lanes per node

    // padded-CSR build + normalization (amortized over both layers)
    build_kernel    <<<nb_e, 256>>>(ei, e, n);
    node_prep_kernel<<<nb_n, 256>>>(n);

    // layer 1
    mm_kernel<false, false><<<nb_m, 256>>>(x, W1, nullptr, dis, tmp, n);
    agg_kernel<true>       <<<nb_g, 256>>>(tmp4, acc16, nullptr, n);

    // layer 2 (b1+ReLU fused into GEMM load; b2+ReLU fused into agg epilogue)
    mm_kernel<true, true>  <<<nb_m, 256>>>(acc16, W2, b1, dis, tmp, n);
    agg_kernel<false>      <<<nb_g, 256>>>(tmp4, out, b2, n);
}